// round 3
// baseline (speedup 1.0000x reference)
#include <cuda_runtime.h>
#include <math.h>

// GCN: out = relu(Agg(X@W1)+b1) -> relu(Agg(.@W2)+b2) -> @Wl + bl
// Agg(Y)[i] = sum_{e: dst=i} Y[src_e]*dinv[src]*dinv[dst] + Y[i]*dinv[i]^2
// deg[i] = (#edges with dst==i) + 1 (self loop), dinv = rsqrt(deg)

#define N_NODES 100000
#define N_EDGES 1600000
#define F 128
#define NCLS 40

// ---- scratch (device globals; allocation-free) ----
__device__ float g_deg[N_NODES];
__device__ float g_dinv[N_NODES];
__device__ float g_buf1[(size_t)N_NODES * F];  // XW buffer
__device__ float g_buf2[(size_t)N_NODES * F];  // aggregation / hidden buffer

// ------------------------------------------------------------------
// degree + norm
// ------------------------------------------------------------------
__global__ void deg_init_kernel() {
    int i = blockIdx.x * blockDim.x + threadIdx.x;
    if (i < N_NODES) g_deg[i] = 1.0f;  // self loop
}

__global__ void deg_count_kernel(const int* __restrict__ dst) {
    int e = blockIdx.x * blockDim.x + threadIdx.x;
    if (e < N_EDGES) atomicAdd(&g_deg[dst[e]], 1.0f);
}

__global__ void dinv_kernel() {
    int i = blockIdx.x * blockDim.x + threadIdx.x;
    if (i < N_NODES) g_dinv[i] = rsqrtf(g_deg[i]);
}

// ------------------------------------------------------------------
// GEMM: C[N,128] = A[N,128] @ W[128,128]
// block: 64 rows x 128 cols, 256 threads, each thread 8x4 microtile
// ------------------------------------------------------------------
__global__ void __launch_bounds__(256) gemm128_kernel(
    const float* __restrict__ A, const float* __restrict__ W,
    float* __restrict__ C) {
    __shared__ float As[64 * 32];
    __shared__ float Ws[32 * 128];
    int tid = threadIdx.x;
    int row0 = blockIdx.x * 64;
    int tx = tid & 31;   // cols tx*4 .. tx*4+3
    int ty = tid >> 5;   // rows ty*8 .. ty*8+7

    float acc[8][4];
#pragma unroll
    for (int r = 0; r < 8; r++)
#pragma unroll
        for (int c = 0; c < 4; c++) acc[r][c] = 0.0f;

#pragma unroll
    for (int kc = 0; kc < 4; kc++) {
        // load A chunk 64x32 (512 float4, 2 per thread)
#pragma unroll
        for (int i = 0; i < 2; i++) {
            int j = tid + i * 256;
            int r = j >> 3, k4 = j & 7;
            int grow = row0 + r;
            float4 v = make_float4(0.f, 0.f, 0.f, 0.f);
            if (grow < N_NODES)
                v = *(const float4*)(A + (size_t)grow * F + kc * 32 + k4 * 4);
            *(float4*)(As + r * 32 + k4 * 4) = v;
        }
        // load W chunk 32x128 (1024 float4, 4 per thread)
#pragma unroll
        for (int i = 0; i < 4; i++) {
            int j = tid + i * 256;
            int kk = j >> 5, c4 = j & 31;
            *(float4*)(Ws + kk * 128 + c4 * 4) =
                *(const float4*)(W + (size_t)(kc * 32 + kk) * 128 + c4 * 4);
        }
        __syncthreads();
#pragma unroll
        for (int k = 0; k < 32; k++) {
            float4 w = *(float4*)(Ws + k * 128 + tx * 4);
#pragma unroll
            for (int r = 0; r < 8; r++) {
                float a = As[(ty * 8 + r) * 32 + k];
                acc[r][0] += a * w.x;
                acc[r][1] += a * w.y;
                acc[r][2] += a * w.z;
                acc[r][3] += a * w.w;
            }
        }
        __syncthreads();
    }
#pragma unroll
    for (int r = 0; r < 8; r++) {
        int grow = row0 + ty * 8 + r;
        if (grow < N_NODES)
            *(float4*)(C + (size_t)grow * F + tx * 4) =
                make_float4(acc[r][0], acc[r][1], acc[r][2], acc[r][3]);
    }
}

// ------------------------------------------------------------------
// self-loop init: out[i,:] = xw[i,:] * dinv[i]^2
// ------------------------------------------------------------------
__global__ void self_init_kernel(const float* __restrict__ xw,
                                 float* __restrict__ out) {
    int idx = blockIdx.x * blockDim.x + threadIdx.x;  // float4 index
    if (idx >= N_NODES * (F / 4)) return;
    int row = idx >> 5;
    float di = g_dinv[row];
    float s = di * di;
    float4 v = *(const float4*)(xw + (size_t)idx * 4);
    v.x *= s; v.y *= s; v.z *= s; v.w *= s;
    *(float4*)(out + (size_t)idx * 4) = v;
}

// ------------------------------------------------------------------
// edge aggregation: out[dst] += xw[src] * dinv[src]*dinv[dst]
// one warp per edge; lane handles one float4 chunk (32*4 = 128 floats)
// vector reduction red.global.add.v4.f32 (sm_90+)
// ------------------------------------------------------------------
__device__ __forceinline__ void red4(float* p, float4 v) {
    asm volatile("red.global.add.v4.f32 [%0], {%1,%2,%3,%4};"
                 :: "l"(p), "f"(v.x), "f"(v.y), "f"(v.z), "f"(v.w)
                 : "memory");
}

__global__ void __launch_bounds__(256) agg_kernel(
    const float* __restrict__ xw, const int* __restrict__ src,
    const int* __restrict__ dst, float* __restrict__ out) {
    long long t = (long long)blockIdx.x * blockDim.x + threadIdx.x;
    int e = (int)(t >> 5);
    int lane = (int)(t & 31);
    if (e >= N_EDGES) return;
    int s = __ldg(src + e);
    int d = __ldg(dst + e);
    float nm = g_dinv[s] * g_dinv[d];
    float4 v = *(const float4*)(xw + (size_t)s * F + lane * 4);
    v.x *= nm; v.y *= nm; v.z *= nm; v.w *= nm;
    red4(out + (size_t)d * F + lane * 4, v);
}

// ------------------------------------------------------------------
// bias + relu in-place
// ------------------------------------------------------------------
__global__ void bias_relu_kernel(float* __restrict__ h,
                                 const float* __restrict__ b) {
    int idx = blockIdx.x * blockDim.x + threadIdx.x;  // float4 index
    if (idx >= N_NODES * (F / 4)) return;
    int j4 = idx & 31;
    float4 bb = *(const float4*)(b + j4 * 4);
    float4 v = *(float4*)(h + (size_t)idx * 4);
    v.x = fmaxf(v.x + bb.x, 0.f);
    v.y = fmaxf(v.y + bb.y, 0.f);
    v.z = fmaxf(v.z + bb.z, 0.f);
    v.w = fmaxf(v.w + bb.w, 0.f);
    *(float4*)(h + (size_t)idx * 4) = v;
}

// ------------------------------------------------------------------
// classifier: out[N,40] = A[N,128] @ Wl[128,40] + bl
// block: 32 rows, 256 threads; thread = (row ty, 5 cols at tx*5)
// ------------------------------------------------------------------
__global__ void __launch_bounds__(256) cls_kernel(
    const float* __restrict__ A, const float* __restrict__ Wl,
    const float* __restrict__ bl, float* __restrict__ out) {
    __shared__ float Ws[128 * 40];
    __shared__ float As[32 * 128];
    int tid = threadIdx.x;
    int row0 = blockIdx.x * 32;

    // load Wl: 5120 floats = 1280 float4, 5 per thread
#pragma unroll
    for (int i = 0; i < 5; i++) {
        int j = tid + i * 256;
        *(float4*)(Ws + j * 4) = *(const float4*)(Wl + j * 4);
    }
    // load A tile 32x128: 1024 float4, 4 per thread
#pragma unroll
    for (int i = 0; i < 4; i++) {
        int j = tid + i * 256;
        int r = j >> 5, k4 = j & 31;
        int grow = row0 + r;
        float4 v = make_float4(0.f, 0.f, 0.f, 0.f);
        if (grow < N_NODES)
            v = *(const float4*)(A + (size_t)grow * F + k4 * 4);
        *(float4*)(As + r * 128 + k4 * 4) = v;
    }
    __syncthreads();

    int tx = tid & 7;   // cols tx*5 .. tx*5+4
    int ty = tid >> 3;  // row
    float acc[5] = {0.f, 0.f, 0.f, 0.f, 0.f};
#pragma unroll 8
    for (int k = 0; k < 128; k++) {
        float a = As[ty * 128 + k];
#pragma unroll
        for (int c = 0; c < 5; c++) acc[c] += a * Ws[k * 40 + tx * 5 + c];
    }
    int grow = row0 + ty;
    if (grow < N_NODES) {
#pragma unroll
        for (int c = 0; c < 5; c++)
            out[(size_t)grow * NCLS + tx * 5 + c] = acc[c] + bl[tx * 5 + c];
    }
}

// ------------------------------------------------------------------
extern "C" void kernel_launch(void* const* d_in, const int* in_sizes, int n_in,
                              void* d_out, int out_size) {
    const float* X  = (const float*)d_in[0];
    const int*   EI = (const int*)d_in[1];     // [2, E]: src = EI[0:E], dst = EI[E:2E]
    const float* W1 = (const float*)d_in[2];
    const float* b1 = (const float*)d_in[3];
    const float* W2 = (const float*)d_in[4];
    const float* b2 = (const float*)d_in[5];
    const float* Wl = (const float*)d_in[6];
    const float* bl = (const float*)d_in[7];
    float* out = (float*)d_out;

    const int* src = EI;
    const int* dst = EI + N_EDGES;

    float *buf1, *buf2;
    cudaGetSymbolAddress((void**)&buf1, g_buf1);
    cudaGetSymbolAddress((void**)&buf2, g_buf2);

    const int T = 256;
    int nblk_nodes = (N_NODES + T - 1) / T;
    int nblk_edges = (N_EDGES + T - 1) / T;
    int nblk_feat  = (N_NODES * (F / 4) + T - 1) / T;      // 12500
    long long agg_threads = (long long)N_EDGES * 32;
    int nblk_agg   = (int)((agg_threads + T - 1) / T);     // 200000
    int nblk_gemm  = (N_NODES + 63) / 64;                  // 1563
    int nblk_cls   = (N_NODES + 31) / 32;                  // 3125

    // norm
    deg_init_kernel<<<nblk_nodes, T>>>();
    deg_count_kernel<<<nblk_edges, T>>>(dst);
    dinv_kernel<<<nblk_nodes, T>>>();

    // layer 1
    gemm128_kernel<<<nblk_gemm, T>>>(X, W1, buf1);
    self_init_kernel<<<nblk_feat, T>>>(buf1, buf2);
    agg_kernel<<<nblk_agg, T>>>(buf1, src, dst, buf2);
    bias_relu_kernel<<<nblk_feat, T>>>(buf2, b1);

    // layer 2
    gemm128_kernel<<<nblk_gemm, T>>>(buf2, W2, buf1);
    self_init_kernel<<<nblk_feat, T>>>(buf1, buf2);   // buf2 (h1) dead after gemm
    agg_kernel<<<nblk_agg, T>>>(buf1, src, dst, buf2);
    bias_relu_kernel<<<nblk_feat, T>>>(buf2, b2);

    // classifier
    cls_kernel<<<nblk_cls, T>>>(buf2, Wl, bl, out);
}

// round 6
// speedup vs baseline: 1.7863x; 1.7863x over previous
#include <cuda_runtime.h>
#include <math.h>

// GCN: out = relu(Agg(X@W1)+b1) -> relu(Agg(.@W2)+b2) -> @Wl + bl
// Agg via dst-CSR pull: per node, gather xw[src]*dinv[src]*dinv[dst] + self.

#define N_NODES 100000
#define N_EDGES 1600000
#define F 128
#define NCLS 40

#define SCAN_CHUNK 512
#define NBLK_SCAN ((N_NODES + SCAN_CHUNK - 1) / SCAN_CHUNK)  // 196

// ---- scratch (device globals; allocation-free) ----
__device__ float g_dinv[N_NODES];
__device__ int   g_cnt[N_NODES];
__device__ int   g_rowptr[N_NODES + 1];
__device__ int   g_cursor[N_NODES];
__device__ int   g_partial[NBLK_SCAN];
__device__ int   g_eidx[N_EDGES];
__device__ float g_buf1[(size_t)N_NODES * F];
__device__ float g_buf2[(size_t)N_NODES * F];

// ------------------------------------------------------------------
// CSR build: histogram over dst, scan, scatter src indices
// ------------------------------------------------------------------
__global__ void zero_cnt_kernel() {
    int i = blockIdx.x * blockDim.x + threadIdx.x;
    if (i < N_NODES) g_cnt[i] = 0;
}

__global__ void hist_kernel(const int* __restrict__ dst) {
    int e = blockIdx.x * blockDim.x + threadIdx.x;
    if (e < N_EDGES) atomicAdd(&g_cnt[dst[e]], 1);
}

__global__ void dinv_kernel() {
    int i = blockIdx.x * blockDim.x + threadIdx.x;
    if (i < N_NODES) g_dinv[i] = rsqrtf((float)g_cnt[i] + 1.0f);  // +1 self loop
}

// per-chunk sums
__global__ void __launch_bounds__(SCAN_CHUNK) scan_partial_kernel() {
    __shared__ int s[SCAN_CHUNK];
    int t = threadIdx.x;
    int i = blockIdx.x * SCAN_CHUNK + t;
    s[t] = (i < N_NODES) ? g_cnt[i] : 0;
    __syncthreads();
    for (int off = SCAN_CHUNK / 2; off > 0; off >>= 1) {
        if (t < off) s[t] += s[t + off];
        __syncthreads();
    }
    if (t == 0) g_partial[blockIdx.x] = s[0];
}

// exclusive scan of the 196 partials (single block; serial is fine)
__global__ void scan_top_kernel() {
    if (threadIdx.x == 0) {
        int run = 0;
        for (int b = 0; b < NBLK_SCAN; b++) {
            int v = g_partial[b];
            g_partial[b] = run;
            run += v;
        }
        g_rowptr[N_NODES] = run;  // == N_EDGES
    }
}

// per-chunk exclusive scan + base -> row_ptr and cursor
__global__ void __launch_bounds__(SCAN_CHUNK) scan_write_kernel() {
    __shared__ int s[SCAN_CHUNK];
    int t = threadIdx.x;
    int i = blockIdx.x * SCAN_CHUNK + t;
    int v = (i < N_NODES) ? g_cnt[i] : 0;
    s[t] = v;
    __syncthreads();
    // Hillis-Steele inclusive scan
    for (int off = 1; off < SCAN_CHUNK; off <<= 1) {
        int x = (t >= off) ? s[t - off] : 0;
        __syncthreads();
        s[t] += x;
        __syncthreads();
    }
    if (i < N_NODES) {
        int excl = s[t] - v;
        int rp = g_partial[blockIdx.x] + excl;
        g_rowptr[i] = rp;
        g_cursor[i] = rp;
    }
}

__global__ void scatter_kernel(const int* __restrict__ src,
                               const int* __restrict__ dst) {
    int e = blockIdx.x * blockDim.x + threadIdx.x;
    if (e >= N_EDGES) return;
    int d = dst[e];
    int pos = atomicAdd(&g_cursor[d], 1);
    g_eidx[pos] = src[e];
}

// ------------------------------------------------------------------
// GEMM: C[N,128] = A[N,128] @ W[128,128]
// ------------------------------------------------------------------
__global__ void __launch_bounds__(256) gemm128_kernel(
    const float* __restrict__ A, const float* __restrict__ W,
    float* __restrict__ C) {
    __shared__ float As[64 * 32];
    __shared__ float Ws[32 * 128];
    int tid = threadIdx.x;
    int row0 = blockIdx.x * 64;
    int tx = tid & 31;
    int ty = tid >> 5;

    float acc[8][4];
#pragma unroll
    for (int r = 0; r < 8; r++)
#pragma unroll
        for (int c = 0; c < 4; c++) acc[r][c] = 0.0f;

#pragma unroll
    for (int kc = 0; kc < 4; kc++) {
#pragma unroll
        for (int i = 0; i < 2; i++) {
            int j = tid + i * 256;
            int r = j >> 3, k4 = j & 7;
            int grow = row0 + r;
            float4 v = make_float4(0.f, 0.f, 0.f, 0.f);
            if (grow < N_NODES)
                v = *(const float4*)(A + (size_t)grow * F + kc * 32 + k4 * 4);
            *(float4*)(As + r * 32 + k4 * 4) = v;
        }
#pragma unroll
        for (int i = 0; i < 4; i++) {
            int j = tid + i * 256;
            int kk = j >> 5, c4 = j & 31;
            *(float4*)(Ws + kk * 128 + c4 * 4) =
                *(const float4*)(W + (size_t)(kc * 32 + kk) * 128 + c4 * 4);
        }
        __syncthreads();
#pragma unroll
        for (int k = 0; k < 32; k++) {
            float4 w = *(float4*)(Ws + k * 128 + tx * 4);
#pragma unroll
            for (int r = 0; r < 8; r++) {
                float a = As[(ty * 8 + r) * 32 + k];
                acc[r][0] += a * w.x;
                acc[r][1] += a * w.y;
                acc[r][2] += a * w.z;
                acc[r][3] += a * w.w;
            }
        }
        __syncthreads();
    }
#pragma unroll
    for (int r = 0; r < 8; r++) {
        int grow = row0 + ty * 8 + r;
        if (grow < N_NODES)
            *(float4*)(C + (size_t)grow * F + tx * 4) =
                make_float4(acc[r][0], acc[r][1], acc[r][2], acc[r][3]);
    }
}

// ------------------------------------------------------------------
// CSR pull aggregation, fused self-loop + bias + relu.
// one warp per node; lane owns one float4 (128 floats total).
// ------------------------------------------------------------------
__global__ void __launch_bounds__(256) agg_csr_kernel(
    const float* __restrict__ xw, float* __restrict__ out,
    const float* __restrict__ bias) {
    int warp = (blockIdx.x * 256 + threadIdx.x) >> 5;
    int lane = threadIdx.x & 31;
    if (warp >= N_NODES) return;
    int node = warp;

    const float4* __restrict__ xw4 = (const float4*)xw;
    float di = g_dinv[node];

    // self loop
    float4 v = xw4[(size_t)node * 32 + lane];
    float s2 = di * di;
    float4 acc;
    acc.x = v.x * s2; acc.y = v.y * s2; acc.z = v.z * s2; acc.w = v.w * s2;

    int beg = g_rowptr[node];
    int end = g_rowptr[node + 1];

    int j = beg;
    // unroll-2 for MLP
    for (; j + 1 < end; j += 2) {
        int s0 = g_eidx[j];
        int s1 = g_eidx[j + 1];
        float n0 = g_dinv[s0] * di;
        float n1 = g_dinv[s1] * di;
        float4 u0 = xw4[(size_t)s0 * 32 + lane];
        float4 u1 = xw4[(size_t)s1 * 32 + lane];
        acc.x += u0.x * n0; acc.y += u0.y * n0;
        acc.z += u0.z * n0; acc.w += u0.w * n0;
        acc.x += u1.x * n1; acc.y += u1.y * n1;
        acc.z += u1.z * n1; acc.w += u1.w * n1;
    }
    if (j < end) {
        int s0 = g_eidx[j];
        float n0 = g_dinv[s0] * di;
        float4 u0 = xw4[(size_t)s0 * 32 + lane];
        acc.x += u0.x * n0; acc.y += u0.y * n0;
        acc.z += u0.z * n0; acc.w += u0.w * n0;
    }

    float4 bb = ((const float4*)bias)[lane];
    acc.x = fmaxf(acc.x + bb.x, 0.f);
    acc.y = fmaxf(acc.y + bb.y, 0.f);
    acc.z = fmaxf(acc.z + bb.z, 0.f);
    acc.w = fmaxf(acc.w + bb.w, 0.f);
    ((float4*)out)[(size_t)node * 32 + lane] = acc;
}

// ------------------------------------------------------------------
// classifier: out[N,40] = A[N,128] @ Wl[128,40] + bl
// ------------------------------------------------------------------
__global__ void __launch_bounds__(256) cls_kernel(
    const float* __restrict__ A, const float* __restrict__ Wl,
    const float* __restrict__ bl, float* __restrict__ out) {
    __shared__ float Ws[128 * 40];
    __shared__ float As[32 * 128];
    int tid = threadIdx.x;
    int row0 = blockIdx.x * 32;

#pragma unroll
    for (int i = 0; i < 5; i++) {
        int j = tid + i * 256;
        *(float4*)(Ws + j * 4) = *(const float4*)(Wl + j * 4);
    }
#pragma unroll
    for (int i = 0; i < 4; i++) {
        int j = tid + i * 256;
        int r = j >> 5, k4 = j & 31;
        int grow = row0 + r;
        float4 v = make_float4(0.f, 0.f, 0.f, 0.f);
        if (grow < N_NODES)
            v = *(const float4*)(A + (size_t)grow * F + k4 * 4);
        *(float4*)(As + r * 128 + k4 * 4) = v;
    }
    __syncthreads();

    int tx = tid & 7;
    int ty = tid >> 3;
    float acc[5] = {0.f, 0.f, 0.f, 0.f, 0.f};
#pragma unroll 8
    for (int k = 0; k < 128; k++) {
        float a = As[ty * 128 + k];
#pragma unroll
        for (int c = 0; c < 5; c++) acc[c] += a * Ws[k * 40 + tx * 5 + c];
    }
    int grow = row0 + ty;
    if (grow < N_NODES) {
#pragma unroll
        for (int c = 0; c < 5; c++)
            out[(size_t)grow * NCLS + tx * 5 + c] = acc[c] + bl[tx * 5 + c];
    }
}

// ------------------------------------------------------------------
extern "C" void kernel_launch(void* const* d_in, const int* in_sizes, int n_in,
                              void* d_out, int out_size) {
    const float* X  = (const float*)d_in[0];
    const int*   EI = (const int*)d_in[1];   // [2, E]: src | dst
    const float* W1 = (const float*)d_in[2];
    const float* b1 = (const float*)d_in[3];
    const float* W2 = (const float*)d_in[4];
    const float* b2 = (const float*)d_in[5];
    const float* Wl = (const float*)d_in[6];
    const float* bl = (const float*)d_in[7];
    float* out = (float*)d_out;

    const int* src = EI;
    const int* dst = EI + N_EDGES;

    float *buf1, *buf2;
    cudaGetSymbolAddress((void**)&buf1, g_buf1);
    cudaGetSymbolAddress((void**)&buf2, g_buf2);

    const int T = 256;
    int nblk_nodes = (N_NODES + T - 1) / T;
    int nblk_edges = (N_EDGES + T - 1) / T;
    int nblk_gemm  = (N_NODES + 63) / 64;
    int nblk_agg   = (N_NODES * 32 + T - 1) / T;  // warp per node
    int nblk_cls   = (N_NODES + 31) / 32;

    // ---- CSR build + norm ----
    zero_cnt_kernel<<<nblk_nodes, T>>>();
    hist_kernel<<<nblk_edges, T>>>(dst);
    dinv_kernel<<<nblk_nodes, T>>>();
    scan_partial_kernel<<<NBLK_SCAN, SCAN_CHUNK>>>();
    scan_top_kernel<<<1, 32>>>();
    scan_write_kernel<<<NBLK_SCAN, SCAN_CHUNK>>>();
    scatter_kernel<<<nblk_edges, T>>>(src, dst);

    // ---- layer 1 ----
    gemm128_kernel<<<nblk_gemm, T>>>(X, W1, buf1);
    agg_csr_kernel<<<nblk_agg, T>>>(buf1, buf2, b1);

    // ---- layer 2 ----
    gemm128_kernel<<<nblk_gemm, T>>>(buf2, W2, buf1);
    agg_csr_kernel<<<nblk_agg, T>>>(buf1, buf2, b2);

    // ---- classifier ----
    cls_kernel<<<nblk_cls, T>>>(buf2, Wl, bl, out);
}

// round 7
// speedup vs baseline: 2.1885x; 1.2252x over previous
#include <cuda_runtime.h>
#include <math.h>
#include <stdint.h>

// GCN: out = relu(Agg(X@W1)+b1) -> relu(Agg(.@W2)+b2) -> @Wl + bl
// GEMMs on tensor cores (tf32 mma.sync, fp32 accumulate).
// Agg via dst-CSR pull, fused self-loop + bias + relu.

#define N_NODES 100000
#define N_EDGES 1600000
#define F 128
#define NCLS 40

#define SCAN_CHUNK 512
#define NBLK_SCAN ((N_NODES + SCAN_CHUNK - 1) / SCAN_CHUNK)  // 196

// ---- scratch (device globals; allocation-free) ----
__device__ float g_dinv[N_NODES];
__device__ int   g_cnt[N_NODES];
__device__ int   g_rowptr[N_NODES + 1];
__device__ int   g_cursor[N_NODES];
__device__ int   g_partial[NBLK_SCAN];
__device__ int   g_eidx[N_EDGES];
__device__ float g_buf1[(size_t)N_NODES * F];
__device__ float g_buf2[(size_t)N_NODES * F];

// ------------------------------------------------------------------
// CSR build: histogram over dst, scan, scatter src indices
// ------------------------------------------------------------------
__global__ void zero_cnt_kernel() {
    int i = blockIdx.x * blockDim.x + threadIdx.x;
    if (i < N_NODES) g_cnt[i] = 0;
}

__global__ void hist_kernel(const int* __restrict__ dst) {
    int e = blockIdx.x * blockDim.x + threadIdx.x;
    if (e < N_EDGES) atomicAdd(&g_cnt[dst[e]], 1);
}

__global__ void dinv_kernel() {
    int i = blockIdx.x * blockDim.x + threadIdx.x;
    if (i < N_NODES) g_dinv[i] = rsqrtf((float)g_cnt[i] + 1.0f);  // +1 self loop
}

__global__ void __launch_bounds__(SCAN_CHUNK) scan_partial_kernel() {
    __shared__ int s[SCAN_CHUNK];
    int t = threadIdx.x;
    int i = blockIdx.x * SCAN_CHUNK + t;
    s[t] = (i < N_NODES) ? g_cnt[i] : 0;
    __syncthreads();
    for (int off = SCAN_CHUNK / 2; off > 0; off >>= 1) {
        if (t < off) s[t] += s[t + off];
        __syncthreads();
    }
    if (t == 0) g_partial[blockIdx.x] = s[0];
}

__global__ void scan_top_kernel() {
    if (threadIdx.x == 0) {
        int run = 0;
        for (int b = 0; b < NBLK_SCAN; b++) {
            int v = g_partial[b];
            g_partial[b] = run;
            run += v;
        }
        g_rowptr[N_NODES] = run;  // == N_EDGES
    }
}

__global__ void __launch_bounds__(SCAN_CHUNK) scan_write_kernel() {
    __shared__ int s[SCAN_CHUNK];
    int t = threadIdx.x;
    int i = blockIdx.x * SCAN_CHUNK + t;
    int v = (i < N_NODES) ? g_cnt[i] : 0;
    s[t] = v;
    __syncthreads();
    for (int off = 1; off < SCAN_CHUNK; off <<= 1) {
        int x = (t >= off) ? s[t - off] : 0;
        __syncthreads();
        s[t] += x;
        __syncthreads();
    }
    if (i < N_NODES) {
        int excl = s[t] - v;
        int rp = g_partial[blockIdx.x] + excl;
        g_rowptr[i] = rp;
        g_cursor[i] = rp;
    }
}

__global__ void scatter_kernel(const int* __restrict__ src,
                               const int* __restrict__ dst) {
    int e = blockIdx.x * blockDim.x + threadIdx.x;
    if (e >= N_EDGES) return;
    int d = dst[e];
    int pos = atomicAdd(&g_cursor[d], 1);
    g_eidx[pos] = src[e];
}

// ------------------------------------------------------------------
// tf32 tensor-core GEMM: C[N,128] = A[N,128] @ W[128,128]
// block tile 128x128, 256 threads = 8 warps, warp tile 32x64.
// mma.sync.aligned.m16n8k8.row.col.f32.tf32.tf32.f32
// ------------------------------------------------------------------
__device__ __forceinline__ uint32_t f2tf32(float f) {
    uint32_t u;
    asm("cvt.rna.tf32.f32 %0, %1;" : "=r"(u) : "f"(f));
    return u;
}

#define AS_STRIDE 36   // 32 k + pad (mult of 4 for uint4 stores)
#define BS_STRIDE 132  // 128 n + pad

__global__ void __launch_bounds__(256) gemm_tf32_kernel(
    const float* __restrict__ A, const float* __restrict__ W,
    float* __restrict__ C) {
    __shared__ uint32_t As[128 * AS_STRIDE];  // 18 KB (tf32 bits)
    __shared__ uint32_t Bs[32 * BS_STRIDE];   // 16.5 KB

    int tid = threadIdx.x;
    int lane = tid & 31;
    int warp = tid >> 5;
    int wr = warp >> 1;       // warp row 0..3 (rows wr*32)
    int wc = warp & 1;        // warp col 0..1 (cols wc*64)
    int g = lane >> 2;        // groupID 0..7
    int tg = lane & 3;        // thread in group 0..3
    int row0 = blockIdx.x * 128;

    float acc[2][8][4];
#pragma unroll
    for (int tm = 0; tm < 2; tm++)
#pragma unroll
        for (int tn = 0; tn < 8; tn++)
#pragma unroll
            for (int c = 0; c < 4; c++) acc[tm][tn][c] = 0.0f;

#pragma unroll
    for (int kc = 0; kc < 4; kc++) {
        // load A chunk 128x32 -> tf32 bits in As (1024 float4, 4/thread)
#pragma unroll
        for (int i = 0; i < 4; i++) {
            int j = tid + i * 256;
            int r = j >> 3, k4 = j & 7;
            int grow = row0 + r;
            float4 v = make_float4(0.f, 0.f, 0.f, 0.f);
            if (grow < N_NODES)
                v = *(const float4*)(A + (size_t)grow * F + kc * 32 + k4 * 4);
            uint4 u;
            u.x = f2tf32(v.x); u.y = f2tf32(v.y);
            u.z = f2tf32(v.z); u.w = f2tf32(v.w);
            *(uint4*)(As + r * AS_STRIDE + k4 * 4) = u;
        }
        // load W chunk 32x128 -> tf32 bits in Bs
#pragma unroll
        for (int i = 0; i < 4; i++) {
            int j = tid + i * 256;
            int kk = j >> 5, n4 = j & 31;
            float4 v = *(const float4*)(W + (size_t)(kc * 32 + kk) * 128 + n4 * 4);
            uint4 u;
            u.x = f2tf32(v.x); u.y = f2tf32(v.y);
            u.z = f2tf32(v.z); u.w = f2tf32(v.w);
            *(uint4*)(Bs + kk * BS_STRIDE + n4 * 4) = u;
        }
        __syncthreads();

#pragma unroll
        for (int k8 = 0; k8 < 4; k8++) {
            // A fragments for the 2 m16 tiles of this warp
            uint32_t a[2][4];
#pragma unroll
            for (int tm = 0; tm < 2; tm++) {
                int rbase = wr * 32 + tm * 16;
                const uint32_t* ap = As + k8 * 8 + tg;
                a[tm][0] = ap[(rbase + g) * AS_STRIDE];
                a[tm][1] = ap[(rbase + g + 8) * AS_STRIDE];
                a[tm][2] = ap[(rbase + g) * AS_STRIDE + 4];
                a[tm][3] = ap[(rbase + g + 8) * AS_STRIDE + 4];
            }
#pragma unroll
            for (int tn = 0; tn < 8; tn++) {
                int ncol = wc * 64 + tn * 8 + g;
                uint32_t b0 = Bs[(k8 * 8 + tg) * BS_STRIDE + ncol];
                uint32_t b1 = Bs[(k8 * 8 + tg + 4) * BS_STRIDE + ncol];
#pragma unroll
                for (int tm = 0; tm < 2; tm++) {
                    asm volatile(
                        "mma.sync.aligned.m16n8k8.row.col.f32.tf32.tf32.f32 "
                        "{%0,%1,%2,%3}, {%4,%5,%6,%7}, {%8,%9}, {%0,%1,%2,%3};"
                        : "+f"(acc[tm][tn][0]), "+f"(acc[tm][tn][1]),
                          "+f"(acc[tm][tn][2]), "+f"(acc[tm][tn][3])
                        : "r"(a[tm][0]), "r"(a[tm][1]), "r"(a[tm][2]),
                          "r"(a[tm][3]), "r"(b0), "r"(b1));
                }
            }
        }
        __syncthreads();
    }

    // store: c0/c1 -> (row g, cols tg*2, tg*2+1); c2/c3 -> row g+8
#pragma unroll
    for (int tm = 0; tm < 2; tm++) {
#pragma unroll
        for (int tn = 0; tn < 8; tn++) {
            int r = row0 + wr * 32 + tm * 16 + g;
            int c = wc * 64 + tn * 8 + tg * 2;
            if (r < N_NODES)
                *(float2*)(C + (size_t)r * F + c) =
                    make_float2(acc[tm][tn][0], acc[tm][tn][1]);
            if (r + 8 < N_NODES)
                *(float2*)(C + (size_t)(r + 8) * F + c) =
                    make_float2(acc[tm][tn][2], acc[tm][tn][3]);
        }
    }
}

// ------------------------------------------------------------------
// CSR pull aggregation, fused self-loop + bias + relu.
// one warp per node; lane owns one float4.
// ------------------------------------------------------------------
__global__ void __launch_bounds__(256) agg_csr_kernel(
    const float* __restrict__ xw, float* __restrict__ out,
    const float* __restrict__ bias) {
    int warp = (blockIdx.x * 256 + threadIdx.x) >> 5;
    int lane = threadIdx.x & 31;
    if (warp >= N_NODES) return;
    int node = warp;

    const float4* __restrict__ xw4 = (const float4*)xw;
    float di = g_dinv[node];

    float4 v = xw4[(size_t)node * 32 + lane];
    float s2 = di * di;
    float4 acc;
    acc.x = v.x * s2; acc.y = v.y * s2; acc.z = v.z * s2; acc.w = v.w * s2;

    int beg = g_rowptr[node];
    int end = g_rowptr[node + 1];

    int j = beg;
    for (; j + 1 < end; j += 2) {
        int s0 = g_eidx[j];
        int s1 = g_eidx[j + 1];
        float n0 = g_dinv[s0] * di;
        float n1 = g_dinv[s1] * di;
        float4 u0 = xw4[(size_t)s0 * 32 + lane];
        float4 u1 = xw4[(size_t)s1 * 32 + lane];
        acc.x += u0.x * n0; acc.y += u0.y * n0;
        acc.z += u0.z * n0; acc.w += u0.w * n0;
        acc.x += u1.x * n1; acc.y += u1.y * n1;
        acc.z += u1.z * n1; acc.w += u1.w * n1;
    }
    if (j < end) {
        int s0 = g_eidx[j];
        float n0 = g_dinv[s0] * di;
        float4 u0 = xw4[(size_t)s0 * 32 + lane];
        acc.x += u0.x * n0; acc.y += u0.y * n0;
        acc.z += u0.z * n0; acc.w += u0.w * n0;
    }

    float4 bb = ((const float4*)bias)[lane];
    acc.x = fmaxf(acc.x + bb.x, 0.f);
    acc.y = fmaxf(acc.y + bb.y, 0.f);
    acc.z = fmaxf(acc.z + bb.z, 0.f);
    acc.w = fmaxf(acc.w + bb.w, 0.f);
    ((float4*)out)[(size_t)node * 32 + lane] = acc;
}

// ------------------------------------------------------------------
// classifier: out[N,40] = A[N,128] @ Wl[128,40] + bl
// ------------------------------------------------------------------
__global__ void __launch_bounds__(256) cls_kernel(
    const float* __restrict__ A, const float* __restrict__ Wl,
    const float* __restrict__ bl, float* __restrict__ out) {
    __shared__ float Ws[128 * 40];
    __shared__ float As[32 * 128];
    int tid = threadIdx.x;
    int row0 = blockIdx.x * 32;

#pragma unroll
    for (int i = 0; i < 5; i++) {
        int j = tid + i * 256;
        *(float4*)(Ws + j * 4) = *(const float4*)(Wl + j * 4);
    }
#pragma unroll
    for (int i = 0; i < 4; i++) {
        int j = tid + i * 256;
        int r = j >> 5, k4 = j & 31;
        int grow = row0 + r;
        float4 v = make_float4(0.f, 0.f, 0.f, 0.f);
        if (grow < N_NODES)
            v = *(const float4*)(A + (size_t)grow * F + k4 * 4);
        *(float4*)(As + r * 128 + k4 * 4) = v;
    }
    __syncthreads();

    int tx = tid & 7;
    int ty = tid >> 3;
    float acc[5] = {0.f, 0.f, 0.f, 0.f, 0.f};
#pragma unroll 8
    for (int k = 0; k < 128; k++) {
        float a = As[ty * 128 + k];
#pragma unroll
        for (int c = 0; c < 5; c++) acc[c] += a * Ws[k * 40 + tx * 5 + c];
    }
    int grow = row0 + ty;
    if (grow < N_NODES) {
#pragma unroll
        for (int c = 0; c < 5; c++)
            out[(size_t)grow * NCLS + tx * 5 + c] = acc[c] + bl[tx * 5 + c];
    }
}

// ------------------------------------------------------------------
extern "C" void kernel_launch(void* const* d_in, const int* in_sizes, int n_in,
                              void* d_out, int out_size) {
    const float* X  = (const float*)d_in[0];
    const int*   EI = (const int*)d_in[1];   // [2, E]: src | dst
    const float* W1 = (const float*)d_in[2];
    const float* b1 = (const float*)d_in[3];
    const float* W2 = (const float*)d_in[4];
    const float* b2 = (const float*)d_in[5];
    const float* Wl = (const float*)d_in[6];
    const float* bl = (const float*)d_in[7];
    float* out = (float*)d_out;

    const int* src = EI;
    const int* dst = EI + N_EDGES;

    float *buf1, *buf2;
    cudaGetSymbolAddress((void**)&buf1, g_buf1);
    cudaGetSymbolAddress((void**)&buf2, g_buf2);

    const int T = 256;
    int nblk_nodes = (N_NODES + T - 1) / T;
    int nblk_edges = (N_EDGES + T - 1) / T;
    int nblk_gemm  = (N_NODES + 127) / 128;       // 782
    int nblk_agg   = (N_NODES * 32 + T - 1) / T;  // warp per node
    int nblk_cls   = (N_NODES + 31) / 32;

    // ---- CSR build + norm ----
    zero_cnt_kernel<<<nblk_nodes, T>>>();
    hist_kernel<<<nblk_edges, T>>>(dst);
    dinv_kernel<<<nblk_nodes, T>>>();
    scan_partial_kernel<<<NBLK_SCAN, SCAN_CHUNK>>>();
    scan_top_kernel<<<1, 32>>>();
    scan_write_kernel<<<NBLK_SCAN, SCAN_CHUNK>>>();
    scatter_kernel<<<nblk_edges, T>>>(src, dst);

    // ---- layer 1 ----
    gemm_tf32_kernel<<<nblk_gemm, T>>>(X, W1, buf1);
    agg_csr_kernel<<<nblk_agg, T>>>(buf1, buf2, b1);

    // ---- layer 2 ----
    gemm_tf32_kernel<<<nblk_gemm, T>>>(buf2, W2, buf1);
    agg_csr_kernel<<<nblk_agg, T>>>(buf1, buf2, b2);

    // ---- classifier ----
    cls_kernel<<<nblk_cls, T>>>(buf2, Wl, bl, out);
}

// round 8
// speedup vs baseline: 2.4340x; 1.1122x over previous
#include <cuda_runtime.h>
#include <cuda_fp16.h>
#include <math.h>
#include <stdint.h>

// GCN: out = relu(Agg(X@W1)+b1) -> relu(Agg(.@W2)+b2) -> @Wl + bl
// GEMMs: tf32 mma.sync (fp32 accum), epilogue writes fp16 messages.
// Agg: dst-CSR pull over fp16 messages, fp32 accumulate, fused bias+relu.
// CSR build overlapped with GEMM1 on a second stream.

#define N_NODES 100000
#define N_EDGES 1600000
#define F 128
#define NCLS 40

#define SCAN_CHUNK 512
#define NBLK_SCAN ((N_NODES + SCAN_CHUNK - 1) / SCAN_CHUNK)  // 196

// ---- scratch (device globals; allocation-free) ----
__device__ float  g_dinv[N_NODES];
__device__ int    g_cnt[N_NODES];
__device__ int    g_rowptr[N_NODES + 1];
__device__ int    g_cursor[N_NODES];
__device__ int    g_partial[NBLK_SCAN];
__device__ int    g_eidx[N_EDGES];
__device__ __half g_hbuf[(size_t)N_NODES * F];  // fp16 xw messages
__device__ float  g_buf1[(size_t)N_NODES * F];  // fp32 hidden
__device__ float  g_buf2[(size_t)N_NODES * F];  // fp32 hidden

// ------------------------------------------------------------------
// CSR build: histogram over dst, scan, scatter src indices
// ------------------------------------------------------------------
__global__ void zero_cnt_kernel() {
    int i = blockIdx.x * blockDim.x + threadIdx.x;
    if (i < N_NODES) g_cnt[i] = 0;
}

__global__ void hist_kernel(const int* __restrict__ dst) {
    int e = blockIdx.x * blockDim.x + threadIdx.x;
    if (e < N_EDGES) atomicAdd(&g_cnt[dst[e]], 1);
}

__global__ void dinv_kernel() {
    int i = blockIdx.x * blockDim.x + threadIdx.x;
    if (i < N_NODES) g_dinv[i] = rsqrtf((float)g_cnt[i] + 1.0f);  // +1 self loop
}

__global__ void __launch_bounds__(SCAN_CHUNK) scan_partial_kernel() {
    __shared__ int s[SCAN_CHUNK];
    int t = threadIdx.x;
    int i = blockIdx.x * SCAN_CHUNK + t;
    s[t] = (i < N_NODES) ? g_cnt[i] : 0;
    __syncthreads();
    for (int off = SCAN_CHUNK / 2; off > 0; off >>= 1) {
        if (t < off) s[t] += s[t + off];
        __syncthreads();
    }
    if (t == 0) g_partial[blockIdx.x] = s[0];
}

__global__ void scan_top_kernel() {
    if (threadIdx.x == 0) {
        int run = 0;
        for (int b = 0; b < NBLK_SCAN; b++) {
            int v = g_partial[b];
            g_partial[b] = run;
            run += v;
        }
        g_rowptr[N_NODES] = run;  // == N_EDGES
    }
}

__global__ void __launch_bounds__(SCAN_CHUNK) scan_write_kernel() {
    __shared__ int s[SCAN_CHUNK];
    int t = threadIdx.x;
    int i = blockIdx.x * SCAN_CHUNK + t;
    int v = (i < N_NODES) ? g_cnt[i] : 0;
    s[t] = v;
    __syncthreads();
    for (int off = 1; off < SCAN_CHUNK; off <<= 1) {
        int x = (t >= off) ? s[t - off] : 0;
        __syncthreads();
        s[t] += x;
        __syncthreads();
    }
    if (i < N_NODES) {
        int excl = s[t] - v;
        int rp = g_partial[blockIdx.x] + excl;
        g_rowptr[i] = rp;
        g_cursor[i] = rp;
    }
}

__global__ void scatter_kernel(const int* __restrict__ src,
                               const int* __restrict__ dst) {
    int e = blockIdx.x * blockDim.x + threadIdx.x;
    if (e >= N_EDGES) return;
    int d = dst[e];
    int pos = atomicAdd(&g_cursor[d], 1);
    g_eidx[pos] = src[e];
}

// ------------------------------------------------------------------
// tf32 tensor-core GEMM: C16[N,128] = A[N,128] @ W[128,128], fp16 out
// block tile 128x128, 256 threads = 8 warps, warp tile 32x64.
// ------------------------------------------------------------------
__device__ __forceinline__ uint32_t f2tf32(float f) {
    uint32_t u;
    asm("cvt.rna.tf32.f32 %0, %1;" : "=r"(u) : "f"(f));
    return u;
}

#define AS_STRIDE 36   // 32 k + pad
#define BS_STRIDE 132  // 128 n + pad

__global__ void __launch_bounds__(256) gemm_tf32_kernel(
    const float* __restrict__ A, const float* __restrict__ W,
    __half* __restrict__ C) {
    __shared__ uint32_t As[128 * AS_STRIDE];
    __shared__ uint32_t Bs[32 * BS_STRIDE];

    int tid = threadIdx.x;
    int lane = tid & 31;
    int warp = tid >> 5;
    int wr = warp >> 1;
    int wc = warp & 1;
    int g = lane >> 2;
    int tg = lane & 3;
    int row0 = blockIdx.x * 128;

    float acc[2][8][4];
#pragma unroll
    for (int tm = 0; tm < 2; tm++)
#pragma unroll
        for (int tn = 0; tn < 8; tn++)
#pragma unroll
            for (int c = 0; c < 4; c++) acc[tm][tn][c] = 0.0f;

#pragma unroll
    for (int kc = 0; kc < 4; kc++) {
#pragma unroll
        for (int i = 0; i < 4; i++) {
            int j = tid + i * 256;
            int r = j >> 3, k4 = j & 7;
            int grow = row0 + r;
            float4 v = make_float4(0.f, 0.f, 0.f, 0.f);
            if (grow < N_NODES)
                v = *(const float4*)(A + (size_t)grow * F + kc * 32 + k4 * 4);
            uint4 u;
            u.x = f2tf32(v.x); u.y = f2tf32(v.y);
            u.z = f2tf32(v.z); u.w = f2tf32(v.w);
            *(uint4*)(As + r * AS_STRIDE + k4 * 4) = u;
        }
#pragma unroll
        for (int i = 0; i < 4; i++) {
            int j = tid + i * 256;
            int kk = j >> 5, n4 = j & 31;
            float4 v = *(const float4*)(W + (size_t)(kc * 32 + kk) * 128 + n4 * 4);
            uint4 u;
            u.x = f2tf32(v.x); u.y = f2tf32(v.y);
            u.z = f2tf32(v.z); u.w = f2tf32(v.w);
            *(uint4*)(Bs + kk * BS_STRIDE + n4 * 4) = u;
        }
        __syncthreads();

#pragma unroll
        for (int k8 = 0; k8 < 4; k8++) {
            uint32_t a[2][4];
#pragma unroll
            for (int tm = 0; tm < 2; tm++) {
                int rbase = wr * 32 + tm * 16;
                const uint32_t* ap = As + k8 * 8 + tg;
                a[tm][0] = ap[(rbase + g) * AS_STRIDE];
                a[tm][1] = ap[(rbase + g + 8) * AS_STRIDE];
                a[tm][2] = ap[(rbase + g) * AS_STRIDE + 4];
                a[tm][3] = ap[(rbase + g + 8) * AS_STRIDE + 4];
            }
#pragma unroll
            for (int tn = 0; tn < 8; tn++) {
                int ncol = wc * 64 + tn * 8 + g;
                uint32_t b0 = Bs[(k8 * 8 + tg) * BS_STRIDE + ncol];
                uint32_t b1 = Bs[(k8 * 8 + tg + 4) * BS_STRIDE + ncol];
#pragma unroll
                for (int tm = 0; tm < 2; tm++) {
                    asm volatile(
                        "mma.sync.aligned.m16n8k8.row.col.f32.tf32.tf32.f32 "
                        "{%0,%1,%2,%3}, {%4,%5,%6,%7}, {%8,%9}, {%0,%1,%2,%3};"
                        : "+f"(acc[tm][tn][0]), "+f"(acc[tm][tn][1]),
                          "+f"(acc[tm][tn][2]), "+f"(acc[tm][tn][3])
                        : "r"(a[tm][0]), "r"(a[tm][1]), "r"(a[tm][2]),
                          "r"(a[tm][3]), "r"(b0), "r"(b1));
                }
            }
        }
        __syncthreads();
    }

#pragma unroll
    for (int tm = 0; tm < 2; tm++) {
#pragma unroll
        for (int tn = 0; tn < 8; tn++) {
            int r = row0 + wr * 32 + tm * 16 + g;
            int c = wc * 64 + tn * 8 + tg * 2;
            if (r < N_NODES)
                *(__half2*)(C + (size_t)r * F + c) =
                    __floats2half2_rn(acc[tm][tn][0], acc[tm][tn][1]);
            if (r + 8 < N_NODES)
                *(__half2*)(C + (size_t)(r + 8) * F + c) =
                    __floats2half2_rn(acc[tm][tn][2], acc[tm][tn][3]);
        }
    }
}

// ------------------------------------------------------------------
// CSR pull aggregation over fp16 messages, fp32 accumulate,
// fused self-loop + bias + relu. one warp per node; lane owns 4 halfs.
// ------------------------------------------------------------------
__device__ __forceinline__ void acc_row(float4& acc, const __half* p, float nm) {
    uint2 u = *(const uint2*)p;
    __half2 h0 = *(__half2*)&u.x;
    __half2 h1 = *(__half2*)&u.y;
    float2 f0 = __half22float2(h0);
    float2 f1 = __half22float2(h1);
    acc.x += f0.x * nm; acc.y += f0.y * nm;
    acc.z += f1.x * nm; acc.w += f1.y * nm;
}

__global__ void __launch_bounds__(256) agg_csr_kernel(
    const __half* __restrict__ xw, float* __restrict__ out,
    const float* __restrict__ bias) {
    int warp = (blockIdx.x * 256 + threadIdx.x) >> 5;
    int lane = threadIdx.x & 31;
    if (warp >= N_NODES) return;
    int node = warp;

    float di = g_dinv[node];
    float4 acc = make_float4(0.f, 0.f, 0.f, 0.f);

    // self loop
    acc_row(acc, xw + (size_t)node * F + lane * 4, di * di);

    int beg = g_rowptr[node];
    int end = g_rowptr[node + 1];

    int j = beg;
    for (; j + 3 < end; j += 4) {
        int s0 = g_eidx[j];
        int s1 = g_eidx[j + 1];
        int s2 = g_eidx[j + 2];
        int s3 = g_eidx[j + 3];
        float n0 = g_dinv[s0] * di;
        float n1 = g_dinv[s1] * di;
        float n2 = g_dinv[s2] * di;
        float n3 = g_dinv[s3] * di;
        acc_row(acc, xw + (size_t)s0 * F + lane * 4, n0);
        acc_row(acc, xw + (size_t)s1 * F + lane * 4, n1);
        acc_row(acc, xw + (size_t)s2 * F + lane * 4, n2);
        acc_row(acc, xw + (size_t)s3 * F + lane * 4, n3);
    }
    for (; j < end; j++) {
        int s0 = g_eidx[j];
        acc_row(acc, xw + (size_t)s0 * F + lane * 4, g_dinv[s0] * di);
    }

    float4 bb = ((const float4*)bias)[lane];
    acc.x = fmaxf(acc.x + bb.x, 0.f);
    acc.y = fmaxf(acc.y + bb.y, 0.f);
    acc.z = fmaxf(acc.z + bb.z, 0.f);
    acc.w = fmaxf(acc.w + bb.w, 0.f);
    ((float4*)out)[(size_t)node * 32 + lane] = acc;
}

// ------------------------------------------------------------------
// classifier: out[N,40] = A[N,128] @ Wl[128,40] + bl
// ------------------------------------------------------------------
__global__ void __launch_bounds__(256) cls_kernel(
    const float* __restrict__ A, const float* __restrict__ Wl,
    const float* __restrict__ bl, float* __restrict__ out) {
    __shared__ float Ws[128 * 40];
    __shared__ float As[32 * 128];
    int tid = threadIdx.x;
    int row0 = blockIdx.x * 32;

#pragma unroll
    for (int i = 0; i < 5; i++) {
        int j = tid + i * 256;
        *(float4*)(Ws + j * 4) = *(const float4*)(Wl + j * 4);
    }
#pragma unroll
    for (int i = 0; i < 4; i++) {
        int j = tid + i * 256;
        int r = j >> 5, k4 = j & 31;
        int grow = row0 + r;
        float4 v = make_float4(0.f, 0.f, 0.f, 0.f);
        if (grow < N_NODES)
            v = *(const float4*)(A + (size_t)grow * F + k4 * 4);
        *(float4*)(As + r * 128 + k4 * 4) = v;
    }
    __syncthreads();

    int tx = tid & 7;
    int ty = tid >> 3;
    float acc[5] = {0.f, 0.f, 0.f, 0.f, 0.f};
#pragma unroll 8
    for (int k = 0; k < 128; k++) {
        float a = As[ty * 128 + k];
#pragma unroll
        for (int c = 0; c < 5; c++) acc[c] += a * Ws[k * 40 + tx * 5 + c];
    }
    int grow = row0 + ty;
    if (grow < N_NODES) {
#pragma unroll
        for (int c = 0; c < 5; c++)
            out[(size_t)grow * NCLS + tx * 5 + c] = acc[c] + bl[tx * 5 + c];
    }
}

// ------------------------------------------------------------------
extern "C" void kernel_launch(void* const* d_in, const int* in_sizes, int n_in,
                              void* d_out, int out_size) {
    const float* X  = (const float*)d_in[0];
    const int*   EI = (const int*)d_in[1];   // [2, E]: src | dst
    const float* W1 = (const float*)d_in[2];
    const float* b1 = (const float*)d_in[3];
    const float* W2 = (const float*)d_in[4];
    const float* b2 = (const float*)d_in[5];
    const float* Wl = (const float*)d_in[6];
    const float* bl = (const float*)d_in[7];
    float* out = (float*)d_out;

    const int* src = EI;
    const int* dst = EI + N_EDGES;

    float *buf1, *buf2;
    __half* hbuf;
    cudaGetSymbolAddress((void**)&buf1, g_buf1);
    cudaGetSymbolAddress((void**)&buf2, g_buf2);
    cudaGetSymbolAddress((void**)&hbuf, g_hbuf);

    // side stream + fork/join events (created once; GPU work per call is
    // identical and deterministic)
    static cudaStream_t s2 = nullptr;
    static cudaEvent_t evF = nullptr, evJ = nullptr;
    if (s2 == nullptr) {
        cudaStreamCreateWithFlags(&s2, cudaStreamNonBlocking);
        cudaEventCreateWithFlags(&evF, cudaEventDisableTiming);
        cudaEventCreateWithFlags(&evJ, cudaEventDisableTiming);
    }

    const int T = 256;
    int nblk_nodes = (N_NODES + T - 1) / T;
    int nblk_edges = (N_EDGES + T - 1) / T;
    int nblk_gemm  = (N_NODES + 127) / 128;
    int nblk_agg   = (N_NODES * 32 + T - 1) / T;
    int nblk_cls   = (N_NODES + 31) / 32;

    // ---- fork: CSR build + norm on s2, GEMM1 on main stream ----
    cudaEventRecord(evF, 0);
    cudaStreamWaitEvent(s2, evF, 0);

    zero_cnt_kernel<<<nblk_nodes, T, 0, s2>>>();
    hist_kernel<<<nblk_edges, T, 0, s2>>>(dst);
    dinv_kernel<<<nblk_nodes, T, 0, s2>>>();
    scan_partial_kernel<<<NBLK_SCAN, SCAN_CHUNK, 0, s2>>>();
    scan_top_kernel<<<1, 32, 0, s2>>>();
    scan_write_kernel<<<NBLK_SCAN, SCAN_CHUNK, 0, s2>>>();
    scatter_kernel<<<nblk_edges, T, 0, s2>>>(src, dst);
    cudaEventRecord(evJ, s2);

    gemm_tf32_kernel<<<nblk_gemm, T>>>(X, W1, hbuf);

    // ---- join ----
    cudaStreamWaitEvent(0, evJ, 0);

    // ---- layer 1 agg ----
    agg_csr_kernel<<<nblk_agg, T>>>(hbuf, buf2, b1);

    // ---- layer 2 ----
    gemm_tf32_kernel<<<nblk_gemm, T>>>(buf2, W2, hbuf);
    agg_csr_kernel<<<nblk_agg, T>>>(hbuf, buf1, b2);

    // ---- classifier ----
    cls_kernel<<<nblk_cls, T>>>(buf1, Wl, bl, out);
}

// round 12
// speedup vs baseline: 2.9738x; 1.2218x over previous
#include <cuda_runtime.h>
#include <cuda_fp16.h>
#include <math.h>
#include <stdint.h>

// GCN: out = relu(Agg(X@W1)+b1) -> relu(Agg(.@W2)+b2) -> @Wl + bl
// GEMMs: tf32 mma.sync (fp32 accum), epilogue writes fp16 messages.
// Agg: dst-CSR pull over fp16 messages with pre-packed (src, norm) edges.
// Classifier: tf32 mma. CSR build overlapped with GEMM1 on a second stream.

#define N_NODES 100000
#define N_EDGES 1600000
#define F 128
#define NCLS 40

#define SCAN_CHUNK 512
#define NBLK_SCAN ((N_NODES + SCAN_CHUNK - 1) / SCAN_CHUNK)  // 196

// ---- scratch (device globals; allocation-free) ----
__device__ float  g_dinv[N_NODES];
__device__ int    g_cnt[N_NODES];
__device__ int    g_rowptr[N_NODES + 1];
__device__ int    g_cursor[N_NODES];
__device__ int    g_partial[NBLK_SCAN];
__device__ int2   g_epack[N_EDGES];             // (src, norm bits)
__device__ __half g_hbuf[(size_t)N_NODES * F];  // fp16 xw messages
__device__ float  g_buf1[(size_t)N_NODES * F];  // fp32 hidden
__device__ float  g_buf2[(size_t)N_NODES * F];  // fp32 hidden

// ------------------------------------------------------------------
// CSR build: histogram over dst, scan, scatter (src, norm)
// ------------------------------------------------------------------
__global__ void zero_cnt_kernel() {
    int i = blockIdx.x * blockDim.x + threadIdx.x;
    if (i < N_NODES) g_cnt[i] = 0;
}

__global__ void hist_kernel(const int* __restrict__ dst) {
    int e = blockIdx.x * blockDim.x + threadIdx.x;
    if (e < N_EDGES) atomicAdd(&g_cnt[dst[e]], 1);
}

__global__ void dinv_kernel() {
    int i = blockIdx.x * blockDim.x + threadIdx.x;
    if (i < N_NODES) g_dinv[i] = rsqrtf((float)g_cnt[i] + 1.0f);  // +1 self loop
}

__global__ void __launch_bounds__(SCAN_CHUNK) scan_partial_kernel() {
    __shared__ int s[SCAN_CHUNK];
    int t = threadIdx.x;
    int i = blockIdx.x * SCAN_CHUNK + t;
    s[t] = (i < N_NODES) ? g_cnt[i] : 0;
    __syncthreads();
    for (int off = SCAN_CHUNK / 2; off > 0; off >>= 1) {
        if (t < off) s[t] += s[t + off];
        __syncthreads();
    }
    if (t == 0) g_partial[blockIdx.x] = s[0];
}

__global__ void scan_top_kernel() {
    if (threadIdx.x == 0) {
        int run = 0;
        for (int b = 0; b < NBLK_SCAN; b++) {
            int v = g_partial[b];
            g_partial[b] = run;
            run += v;
        }
        g_rowptr[N_NODES] = run;  // == N_EDGES
    }
}

__global__ void __launch_bounds__(SCAN_CHUNK) scan_write_kernel() {
    __shared__ int s[SCAN_CHUNK];
    int t = threadIdx.x;
    int i = blockIdx.x * SCAN_CHUNK + t;
    int v = (i < N_NODES) ? g_cnt[i] : 0;
    s[t] = v;
    __syncthreads();
    for (int off = 1; off < SCAN_CHUNK; off <<= 1) {
        int x = (t >= off) ? s[t - off] : 0;
        __syncthreads();
        s[t] += x;
        __syncthreads();
    }
    if (i < N_NODES) {
        int excl = s[t] - v;
        int rp = g_partial[blockIdx.x] + excl;
        g_rowptr[i] = rp;
        g_cursor[i] = rp;
    }
}

__global__ void scatter_kernel(const int* __restrict__ src,
                               const int* __restrict__ dst) {
    int e = blockIdx.x * blockDim.x + threadIdx.x;
    if (e >= N_EDGES) return;
    int s = src[e];
    int d = dst[e];
    float nm = g_dinv[s] * g_dinv[d];
    int pos = atomicAdd(&g_cursor[d], 1);
    g_epack[pos] = make_int2(s, __float_as_int(nm));
}

// ------------------------------------------------------------------
// tf32 tensor-core GEMM: C16[N,128] = A[N,128] @ W[128,128], fp16 out
// ------------------------------------------------------------------
__device__ __forceinline__ uint32_t f2tf32(float f) {
    uint32_t u;
    asm("cvt.rna.tf32.f32 %0, %1;" : "=r"(u) : "f"(f));
    return u;
}

#define AS_STRIDE 36   // 32 k + pad
#define BS_STRIDE 132  // 128 n + pad

__global__ void __launch_bounds__(256) gemm_tf32_kernel(
    const float* __restrict__ A, const float* __restrict__ W,
    __half* __restrict__ C) {
    __shared__ uint32_t As[128 * AS_STRIDE];
    __shared__ uint32_t Bs[32 * BS_STRIDE];

    int tid = threadIdx.x;
    int lane = tid & 31;
    int warp = tid >> 5;
    int wr = warp >> 1;
    int wc = warp & 1;
    int g = lane >> 2;
    int tg = lane & 3;
    int row0 = blockIdx.x * 128;

    float acc[2][8][4];
#pragma unroll
    for (int tm = 0; tm < 2; tm++)
#pragma unroll
        for (int tn = 0; tn < 8; tn++)
#pragma unroll
            for (int c = 0; c < 4; c++) acc[tm][tn][c] = 0.0f;

#pragma unroll
    for (int kc = 0; kc < 4; kc++) {
#pragma unroll
        for (int i = 0; i < 4; i++) {
            int j = tid + i * 256;
            int r = j >> 3, k4 = j & 7;
            int grow = row0 + r;
            float4 v = make_float4(0.f, 0.f, 0.f, 0.f);
            if (grow < N_NODES)
                v = *(const float4*)(A + (size_t)grow * F + kc * 32 + k4 * 4);
            uint4 u;
            u.x = f2tf32(v.x); u.y = f2tf32(v.y);
            u.z = f2tf32(v.z); u.w = f2tf32(v.w);
            *(uint4*)(As + r * AS_STRIDE + k4 * 4) = u;
        }
#pragma unroll
        for (int i = 0; i < 4; i++) {
            int j = tid + i * 256;
            int kk = j >> 5, n4 = j & 31;
            float4 v = *(const float4*)(W + (size_t)(kc * 32 + kk) * 128 + n4 * 4);
            uint4 u;
            u.x = f2tf32(v.x); u.y = f2tf32(v.y);
            u.z = f2tf32(v.z); u.w = f2tf32(v.w);
            *(uint4*)(Bs + kk * BS_STRIDE + n4 * 4) = u;
        }
        __syncthreads();

#pragma unroll
        for (int k8 = 0; k8 < 4; k8++) {
            uint32_t a[2][4];
#pragma unroll
            for (int tm = 0; tm < 2; tm++) {
                int rbase = wr * 32 + tm * 16;
                const uint32_t* ap = As + k8 * 8 + tg;
                a[tm][0] = ap[(rbase + g) * AS_STRIDE];
                a[tm][1] = ap[(rbase + g + 8) * AS_STRIDE];
                a[tm][2] = ap[(rbase + g) * AS_STRIDE + 4];
                a[tm][3] = ap[(rbase + g + 8) * AS_STRIDE + 4];
            }
#pragma unroll
            for (int tn = 0; tn < 8; tn++) {
                int ncol = wc * 64 + tn * 8 + g;
                uint32_t b0 = Bs[(k8 * 8 + tg) * BS_STRIDE + ncol];
                uint32_t b1 = Bs[(k8 * 8 + tg + 4) * BS_STRIDE + ncol];
#pragma unroll
                for (int tm = 0; tm < 2; tm++) {
                    asm volatile(
                        "mma.sync.aligned.m16n8k8.row.col.f32.tf32.tf32.f32 "
                        "{%0,%1,%2,%3}, {%4,%5,%6,%7}, {%8,%9}, {%0,%1,%2,%3};"
                        : "+f"(acc[tm][tn][0]), "+f"(acc[tm][tn][1]),
                          "+f"(acc[tm][tn][2]), "+f"(acc[tm][tn][3])
                        : "r"(a[tm][0]), "r"(a[tm][1]), "r"(a[tm][2]),
                          "r"(a[tm][3]), "r"(b0), "r"(b1));
                }
            }
        }
        __syncthreads();
    }

#pragma unroll
    for (int tm = 0; tm < 2; tm++) {
#pragma unroll
        for (int tn = 0; tn < 8; tn++) {
            int r = row0 + wr * 32 + tm * 16 + g;
            int c = wc * 64 + tn * 8 + tg * 2;
            if (r < N_NODES)
                *(__half2*)(C + (size_t)r * F + c) =
                    __floats2half2_rn(acc[tm][tn][0], acc[tm][tn][1]);
            if (r + 8 < N_NODES)
                *(__half2*)(C + (size_t)(r + 8) * F + c) =
                    __floats2half2_rn(acc[tm][tn][2], acc[tm][tn][3]);
        }
    }
}

// ------------------------------------------------------------------
// CSR pull aggregation over fp16 messages + packed (src, norm) edges.
// fp32 accumulate, fused self-loop + bias + relu. warp per node.
// ------------------------------------------------------------------
__device__ __forceinline__ void acc_row(float4& acc, const __half* p, float nm) {
    uint2 u = *(const uint2*)p;
    __half2 h0 = *(__half2*)&u.x;
    __half2 h1 = *(__half2*)&u.y;
    float2 f0 = __half22float2(h0);
    float2 f1 = __half22float2(h1);
    acc.x += f0.x * nm; acc.y += f0.y * nm;
    acc.z += f1.x * nm; acc.w += f1.y * nm;
}

__global__ void __launch_bounds__(256) agg_csr_kernel(
    const __half* __restrict__ xw, float* __restrict__ out,
    const float* __restrict__ bias) {
    int warp = (blockIdx.x * 256 + threadIdx.x) >> 5;
    int lane = threadIdx.x & 31;
    if (warp >= N_NODES) return;
    int node = warp;

    float di = g_dinv[node];
    float4 acc = make_float4(0.f, 0.f, 0.f, 0.f);

    // self loop
    acc_row(acc, xw + (size_t)node * F + lane * 4, di * di);

    int beg = g_rowptr[node];
    int end = g_rowptr[node + 1];

    int j = beg;
    for (; j + 3 < end; j += 4) {
        int2 p0 = g_epack[j];
        int2 p1 = g_epack[j + 1];
        int2 p2 = g_epack[j + 2];
        int2 p3 = g_epack[j + 3];
        acc_row(acc, xw + (size_t)p0.x * F + lane * 4, __int_as_float(p0.y));
        acc_row(acc, xw + (size_t)p1.x * F + lane * 4, __int_as_float(p1.y));
        acc_row(acc, xw + (size_t)p2.x * F + lane * 4, __int_as_float(p2.y));
        acc_row(acc, xw + (size_t)p3.x * F + lane * 4, __int_as_float(p3.y));
    }
    for (; j < end; j++) {
        int2 p0 = g_epack[j];
        acc_row(acc, xw + (size_t)p0.x * F + lane * 4, __int_as_float(p0.y));
    }

    float4 bb = ((const float4*)bias)[lane];
    acc.x = fmaxf(acc.x + bb.x, 0.f);
    acc.y = fmaxf(acc.y + bb.y, 0.f);
    acc.z = fmaxf(acc.z + bb.z, 0.f);
    acc.w = fmaxf(acc.w + bb.w, 0.f);
    ((float4*)out)[(size_t)node * 32 + lane] = acc;
}

// ------------------------------------------------------------------
// tf32 classifier: out[N,40] = A[N,128] @ Wl[128,40] + bl
// block tile 128 rows, 8 warps x 16 rows, 5 n-tiles (40 cols exactly).
// ------------------------------------------------------------------
#define WS_STRIDE 44  // 40 + pad

__global__ void __launch_bounds__(256) cls_tf32_kernel(
    const float* __restrict__ A, const float* __restrict__ Wl,
    const float* __restrict__ bl, float* __restrict__ out) {
    __shared__ uint32_t As[128 * AS_STRIDE];  // 18 KB
    __shared__ uint32_t Ws[128 * WS_STRIDE];  // 22.5 KB

    int tid = threadIdx.x;
    int lane = tid & 31;
    int warp = tid >> 5;
    int g = lane >> 2;
    int tg = lane & 3;
    int row0 = blockIdx.x * 128;

    // load full Wl (128x40) -> tf32 once
    for (int idx = tid; idx < 128 * 40; idx += 256) {
        int k = idx / 40, n = idx % 40;
        Ws[k * WS_STRIDE + n] = f2tf32(Wl[idx]);
    }

    float acc[5][4];
#pragma unroll
    for (int tn = 0; tn < 5; tn++)
#pragma unroll
        for (int c = 0; c < 4; c++) acc[tn][c] = 0.0f;

#pragma unroll
    for (int kc = 0; kc < 4; kc++) {
#pragma unroll
        for (int i = 0; i < 4; i++) {
            int j = tid + i * 256;
            int r = j >> 3, k4 = j & 7;
            int grow = row0 + r;
            float4 v = make_float4(0.f, 0.f, 0.f, 0.f);
            if (grow < N_NODES)
                v = *(const float4*)(A + (size_t)grow * F + kc * 32 + k4 * 4);
            uint4 u;
            u.x = f2tf32(v.x); u.y = f2tf32(v.y);
            u.z = f2tf32(v.z); u.w = f2tf32(v.w);
            *(uint4*)(As + r * AS_STRIDE + k4 * 4) = u;
        }
        __syncthreads();

#pragma unroll
        for (int k8 = 0; k8 < 4; k8++) {
            int rbase = warp * 16;
            const uint32_t* ap = As + k8 * 8 + tg;
            uint32_t a0 = ap[(rbase + g) * AS_STRIDE];
            uint32_t a1 = ap[(rbase + g + 8) * AS_STRIDE];
            uint32_t a2 = ap[(rbase + g) * AS_STRIDE + 4];
            uint32_t a3 = ap[(rbase + g + 8) * AS_STRIDE + 4];
            int krow = kc * 32 + k8 * 8;
#pragma unroll
            for (int tn = 0; tn < 5; tn++) {
                int ncol = tn * 8 + g;
                uint32_t b0 = Ws[(krow + tg) * WS_STRIDE + ncol];
                uint32_t b1 = Ws[(krow + tg + 4) * WS_STRIDE + ncol];
                asm volatile(
                    "mma.sync.aligned.m16n8k8.row.col.f32.tf32.tf32.f32 "
                    "{%0,%1,%2,%3}, {%4,%5,%6,%7}, {%8,%9}, {%0,%1,%2,%3};"
                    : "+f"(acc[tn][0]), "+f"(acc[tn][1]),
                      "+f"(acc[tn][2]), "+f"(acc[tn][3])
                    : "r"(a0), "r"(a1), "r"(a2), "r"(a3), "r"(b0), "r"(b1));
            }
        }
        __syncthreads();
    }

#pragma unroll
    for (int tn = 0; tn < 5; tn++) {
        int r = row0 + warp * 16 + g;
        int c = tn * 8 + tg * 2;
        float2 bb = *(const float2*)(bl + c);
        if (r < N_NODES)
            *(float2*)(out + (size_t)r * NCLS + c) =
                make_float2(acc[tn][0] + bb.x, acc[tn][1] + bb.y);
        if (r + 8 < N_NODES)
            *(float2*)(out + (size_t)(r + 8) * NCLS + c) =
                make_float2(acc[tn][2] + bb.x, acc[tn][3] + bb.y);
    }
}

// ------------------------------------------------------------------
extern "C" void kernel_launch(void* const* d_in, const int* in_sizes, int n_in,
                              void* d_out, int out_size) {
    const float* X  = (const float*)d_in[0];
    const int*   EI = (const int*)d_in[1];   // [2, E]: src | dst
    const float* W1 = (const float*)d_in[2];
    const float* b1 = (const float*)d_in[3];
    const float* W2 = (const float*)d_in[4];
    const float* b2 = (const float*)d_in[5];
    const float* Wl = (const float*)d_in[6];
    const float* bl = (const float*)d_in[7];
    float* out = (float*)d_out;

    const int* src = EI;
    const int* dst = EI + N_EDGES;

    float *buf1, *buf2;
    __half* hbuf;
    cudaGetSymbolAddress((void**)&buf1, g_buf1);
    cudaGetSymbolAddress((void**)&buf2, g_buf2);
    cudaGetSymbolAddress((void**)&hbuf, g_hbuf);

    static cudaStream_t s2 = nullptr;
    static cudaEvent_t evF = nullptr, evJ = nullptr;
    if (s2 == nullptr) {
        cudaStreamCreateWithFlags(&s2, cudaStreamNonBlocking);
        cudaEventCreateWithFlags(&evF, cudaEventDisableTiming);
        cudaEventCreateWithFlags(&evJ, cudaEventDisableTiming);
    }

    const int T = 256;
    int nblk_nodes = (N_NODES + T - 1) / T;
    int nblk_edges = (N_EDGES + T - 1) / T;
    int nblk_gemm  = (N_NODES + 127) / 128;
    int nblk_agg   = (N_NODES * 32 + T - 1) / T;

    // ---- fork: CSR build + norm on s2, GEMM1 on main stream ----
    cudaEventRecord(evF, 0);
    cudaStreamWaitEvent(s2, evF, 0);

    zero_cnt_kernel<<<nblk_nodes, T, 0, s2>>>();
    hist_kernel<<<nblk_edges, T, 0, s2>>>(dst);
    dinv_kernel<<<nblk_nodes, T, 0, s2>>>();
    scan_partial_kernel<<<NBLK_SCAN, SCAN_CHUNK, 0, s2>>>();
    scan_top_kernel<<<1, 32, 0, s2>>>();
    scan_write_kernel<<<NBLK_SCAN, SCAN_CHUNK, 0, s2>>>();
    scatter_kernel<<<nblk_edges, T, 0, s2>>>(src, dst);
    cudaEventRecord(evJ, s2);

    gemm_tf32_kernel<<<nblk_gemm, T>>>(X, W1, hbuf);

    // ---- join ----
    cudaStreamWaitEvent(0, evJ, 0);

    // ---- layer 1 agg ----
    agg_csr_kernel<<<nblk_agg, T>>>(hbuf, buf2, b1);

    // ---- layer 2 ----
    gemm_tf32_kernel<<<nblk_gemm, T>>>(buf2, W2, hbuf);
    agg_csr_kernel<<<nblk_agg, T>>>(hbuf, buf1, b2);

    // ---- classifier ----
    cls_tf32_kernel<<<nblk_gemm, T>>>(buf1, Wl, bl, out);
}

// round 14
// speedup vs baseline: 3.3563x; 1.1286x over previous
#include <cuda_runtime.h>
#include <cuda_fp16.h>
#include <math.h>
#include <stdint.h>

// GCN: out = relu(Agg(X@W1)+b1) -> relu(Agg(.@W2)+b2) -> @Wl + bl
// GEMM1: tf32 mma (fp32 X), writes fp16 messages.
// Agg: dst-CSR pull over fp16 messages, packed (src,norm), writes fp16 hidden.
// GEMM2/cls: fp16 m16n8k16 mma (fp32 accum).
// CSR build overlapped with GEMM1 on a second stream.

#define N_NODES 100000
#define N_EDGES 1600000
#define F 128
#define NCLS 40

#define SCAN_CHUNK 512
#define NBLK_SCAN ((N_NODES + SCAN_CHUNK - 1) / SCAN_CHUNK)  // 196

// ---- scratch (device globals; allocation-free) ----
__device__ float  g_dinv[N_NODES];
__device__ int    g_cnt[N_NODES];
__device__ int    g_rowptr[N_NODES + 1];
__device__ int    g_cursor[N_NODES];
__device__ int    g_partial[NBLK_SCAN];
__device__ int2   g_epack[N_EDGES];             // (src, norm bits)
__device__ __half g_hbuf[(size_t)N_NODES * F];  // fp16 xw messages
__device__ __half g_hid[(size_t)N_NODES * F];   // fp16 hidden states

// ------------------------------------------------------------------
// CSR build
// ------------------------------------------------------------------
__global__ void zero_cnt_kernel() {
    int i = blockIdx.x * blockDim.x + threadIdx.x;
    if (i < N_NODES) g_cnt[i] = 0;
}

__global__ void hist_kernel(const int* __restrict__ dst) {
    int e = blockIdx.x * blockDim.x + threadIdx.x;
    if (e < N_EDGES) atomicAdd(&g_cnt[dst[e]], 1);
}

// fused: dinv + per-chunk sums
__global__ void __launch_bounds__(SCAN_CHUNK) dinv_partial_kernel() {
    __shared__ int s[SCAN_CHUNK];
    int t = threadIdx.x;
    int i = blockIdx.x * SCAN_CHUNK + t;
    int c = (i < N_NODES) ? g_cnt[i] : 0;
    if (i < N_NODES) g_dinv[i] = rsqrtf((float)c + 1.0f);  // +1 self loop
    s[t] = c;
    __syncthreads();
    for (int off = SCAN_CHUNK / 2; off > 0; off >>= 1) {
        if (t < off) s[t] += s[t + off];
        __syncthreads();
    }
    if (t == 0) g_partial[blockIdx.x] = s[0];
}

__global__ void scan_top_kernel() {
    if (threadIdx.x == 0) {
        int run = 0;
        for (int b = 0; b < NBLK_SCAN; b++) {
            int v = g_partial[b];
            g_partial[b] = run;
            run += v;
        }
        g_rowptr[N_NODES] = run;  // == N_EDGES
    }
}

__global__ void __launch_bounds__(SCAN_CHUNK) scan_write_kernel() {
    __shared__ int s[SCAN_CHUNK];
    int t = threadIdx.x;
    int i = blockIdx.x * SCAN_CHUNK + t;
    int v = (i < N_NODES) ? g_cnt[i] : 0;
    s[t] = v;
    __syncthreads();
    for (int off = 1; off < SCAN_CHUNK; off <<= 1) {
        int x = (t >= off) ? s[t - off] : 0;
        __syncthreads();
        s[t] += x;
        __syncthreads();
    }
    if (i < N_NODES) {
        int excl = s[t] - v;
        int rp = g_partial[blockIdx.x] + excl;
        g_rowptr[i] = rp;
        g_cursor[i] = rp;
    }
}

__global__ void scatter_kernel(const int* __restrict__ src,
                               const int* __restrict__ dst) {
    int e = blockIdx.x * blockDim.x + threadIdx.x;
    if (e >= N_EDGES) return;
    int s = src[e];
    int d = dst[e];
    float nm = g_dinv[s] * g_dinv[d];
    int pos = atomicAdd(&g_cursor[d], 1);
    g_epack[pos] = make_int2(s, __float_as_int(nm));
}

// ------------------------------------------------------------------
// tf32 GEMM (layer 1): C16[N,128] = A32[N,128] @ W[128,128], fp16 out
// ------------------------------------------------------------------
__device__ __forceinline__ uint32_t f2tf32(float f) {
    uint32_t u;
    asm("cvt.rna.tf32.f32 %0, %1;" : "=r"(u) : "f"(f));
    return u;
}

__device__ __forceinline__ uint32_t h2bits(__half2 h) {
    return *(uint32_t*)&h;
}

#define AS_STRIDE 36   // tf32: 32 k + pad
#define BS_STRIDE 132  // tf32: 128 n + pad

__global__ void __launch_bounds__(256) gemm_tf32_kernel(
    const float* __restrict__ A, const float* __restrict__ W,
    __half* __restrict__ C) {
    __shared__ uint32_t As[128 * AS_STRIDE];
    __shared__ uint32_t Bs[32 * BS_STRIDE];

    int tid = threadIdx.x;
    int lane = tid & 31;
    int warp = tid >> 5;
    int wr = warp >> 1;
    int wc = warp & 1;
    int g = lane >> 2;
    int tg = lane & 3;
    int row0 = blockIdx.x * 128;

    float acc[2][8][4];
#pragma unroll
    for (int tm = 0; tm < 2; tm++)
#pragma unroll
        for (int tn = 0; tn < 8; tn++)
#pragma unroll
            for (int c = 0; c < 4; c++) acc[tm][tn][c] = 0.0f;

#pragma unroll
    for (int kc = 0; kc < 4; kc++) {
#pragma unroll
        for (int i = 0; i < 4; i++) {
            int j = tid + i * 256;
            int r = j >> 3, k4 = j & 7;
            int grow = row0 + r;
            float4 v = make_float4(0.f, 0.f, 0.f, 0.f);
            if (grow < N_NODES)
                v = *(const float4*)(A + (size_t)grow * F + kc * 32 + k4 * 4);
            uint4 u;
            u.x = f2tf32(v.x); u.y = f2tf32(v.y);
            u.z = f2tf32(v.z); u.w = f2tf32(v.w);
            *(uint4*)(As + r * AS_STRIDE + k4 * 4) = u;
        }
#pragma unroll
        for (int i = 0; i < 4; i++) {
            int j = tid + i * 256;
            int kk = j >> 5, n4 = j & 31;
            float4 v = *(const float4*)(W + (size_t)(kc * 32 + kk) * 128 + n4 * 4);
            uint4 u;
            u.x = f2tf32(v.x); u.y = f2tf32(v.y);
            u.z = f2tf32(v.z); u.w = f2tf32(v.w);
            *(uint4*)(Bs + kk * BS_STRIDE + n4 * 4) = u;
        }
        __syncthreads();

#pragma unroll
        for (int k8 = 0; k8 < 4; k8++) {
            uint32_t a[2][4];
#pragma unroll
            for (int tm = 0; tm < 2; tm++) {
                int rbase = wr * 32 + tm * 16;
                const uint32_t* ap = As + k8 * 8 + tg;
                a[tm][0] = ap[(rbase + g) * AS_STRIDE];
                a[tm][1] = ap[(rbase + g + 8) * AS_STRIDE];
                a[tm][2] = ap[(rbase + g) * AS_STRIDE + 4];
                a[tm][3] = ap[(rbase + g + 8) * AS_STRIDE + 4];
            }
#pragma unroll
            for (int tn = 0; tn < 8; tn++) {
                int ncol = wc * 64 + tn * 8 + g;
                uint32_t b0 = Bs[(k8 * 8 + tg) * BS_STRIDE + ncol];
                uint32_t b1 = Bs[(k8 * 8 + tg + 4) * BS_STRIDE + ncol];
#pragma unroll
                for (int tm = 0; tm < 2; tm++) {
                    asm volatile(
                        "mma.sync.aligned.m16n8k8.row.col.f32.tf32.tf32.f32 "
                        "{%0,%1,%2,%3}, {%4,%5,%6,%7}, {%8,%9}, {%0,%1,%2,%3};"
                        : "+f"(acc[tm][tn][0]), "+f"(acc[tm][tn][1]),
                          "+f"(acc[tm][tn][2]), "+f"(acc[tm][tn][3])
                        : "r"(a[tm][0]), "r"(a[tm][1]), "r"(a[tm][2]),
                          "r"(a[tm][3]), "r"(b0), "r"(b1));
                }
            }
        }
        __syncthreads();
    }

#pragma unroll
    for (int tm = 0; tm < 2; tm++) {
#pragma unroll
        for (int tn = 0; tn < 8; tn++) {
            int r = row0 + wr * 32 + tm * 16 + g;
            int c = wc * 64 + tn * 8 + tg * 2;
            if (r < N_NODES)
                *(__half2*)(C + (size_t)r * F + c) =
                    __floats2half2_rn(acc[tm][tn][0], acc[tm][tn][1]);
            if (r + 8 < N_NODES)
                *(__half2*)(C + (size_t)(r + 8) * F + c) =
                    __floats2half2_rn(acc[tm][tn][2], acc[tm][tn][3]);
        }
    }
}

// ------------------------------------------------------------------
// fp16 GEMM (layer 2): C16[N,128] = A16[N,128] @ W[128,128]
// mma.m16n8k16.f16.f16.f32; W converted fp32->fp16 in smem.
// ------------------------------------------------------------------
#define AH_STRIDE 20   // u32 stride: 16 u32 (32 halves) + 4 pad
#define BH_STRIDE 132  // u32 stride: 128 n + pad (half2 pairs along k)

__global__ void __launch_bounds__(256) gemm_f16_kernel(
    const __half* __restrict__ A, const float* __restrict__ W,
    __half* __restrict__ C) {
    __shared__ uint32_t As[128 * AH_STRIDE];  // 10 KB
    __shared__ uint32_t Bs[16 * BH_STRIDE];   // 8.25 KB  (k2 x n half2 pairs)

    int tid = threadIdx.x;
    int lane = tid & 31;
    int warp = tid >> 5;
    int wr = warp >> 1;
    int wc = warp & 1;
    int g = lane >> 2;
    int tg = lane & 3;
    int row0 = blockIdx.x * 128;

    float acc[2][8][4];
#pragma unroll
    for (int tm = 0; tm < 2; tm++)
#pragma unroll
        for (int tn = 0; tn < 8; tn++)
#pragma unroll
            for (int c = 0; c < 4; c++) acc[tm][tn][c] = 0.0f;

#pragma unroll
    for (int kc = 0; kc < 4; kc++) {
        // A chunk 128x32 halves = 512 uint4; 2/thread
#pragma unroll
        for (int i = 0; i < 2; i++) {
            int j = tid + i * 256;
            int r = j >> 2, q = j & 3;
            int grow = row0 + r;
            uint4 v = make_uint4(0, 0, 0, 0);
            if (grow < N_NODES)
                v = *(const uint4*)(A + (size_t)grow * F + kc * 32 + q * 8);
            *(uint2*)(As + r * AH_STRIDE + q * 4) = make_uint2(v.x, v.y);
            *(uint2*)(As + r * AH_STRIDE + q * 4 + 2) = make_uint2(v.z, v.w);
        }
        // B pairs: k2 in [0,16), n in [0,128): 2048 u32; 8/thread
#pragma unroll
        for (int i = 0; i < 8; i++) {
            int j = tid + i * 256;
            int k2 = j >> 7, n = j & 127;
            int krow = kc * 32 + k2 * 2;
            float w0 = W[(size_t)krow * 128 + n];
            float w1 = W[(size_t)(krow + 1) * 128 + n];
            Bs[k2 * BH_STRIDE + n] = h2bits(__floats2half2_rn(w0, w1));
        }
        __syncthreads();

#pragma unroll
        for (int s = 0; s < 2; s++) {  // two k16 steps per chunk
            uint32_t a[2][4];
#pragma unroll
            for (int tm = 0; tm < 2; tm++) {
                int rbase = wr * 32 + tm * 16;
                const uint32_t* ap = As + s * 8 + tg;
                a[tm][0] = ap[(rbase + g) * AH_STRIDE];
                a[tm][1] = ap[(rbase + g + 8) * AH_STRIDE];
                a[tm][2] = ap[(rbase + g) * AH_STRIDE + 4];
                a[tm][3] = ap[(rbase + g + 8) * AH_STRIDE + 4];
            }
#pragma unroll
            for (int tn = 0; tn < 8; tn++) {
                int ncol = wc * 64 + tn * 8 + g;
                uint32_t b0 = Bs[(s * 8 + tg) * BH_STRIDE + ncol];
                uint32_t b1 = Bs[(s * 8 + tg + 4) * BH_STRIDE + ncol];
#pragma unroll
                for (int tm = 0; tm < 2; tm++) {
                    asm volatile(
                        "mma.sync.aligned.m16n8k16.row.col.f32.f16.f16.f32 "
                        "{%0,%1,%2,%3}, {%4,%5,%6,%7}, {%8,%9}, {%0,%1,%2,%3};"
                        : "+f"(acc[tm][tn][0]), "+f"(acc[tm][tn][1]),
                          "+f"(acc[tm][tn][2]), "+f"(acc[tm][tn][3])
                        : "r"(a[tm][0]), "r"(a[tm][1]), "r"(a[tm][2]),
                          "r"(a[tm][3]), "r"(b0), "r"(b1));
                }
            }
        }
        __syncthreads();
    }

#pragma unroll
    for (int tm = 0; tm < 2; tm++) {
#pragma unroll
        for (int tn = 0; tn < 8; tn++) {
            int r = row0 + wr * 32 + tm * 16 + g;
            int c = wc * 64 + tn * 8 + tg * 2;
            if (r < N_NODES)
                *(__half2*)(C + (size_t)r * F + c) =
                    __floats2half2_rn(acc[tm][tn][0], acc[tm][tn][1]);
            if (r + 8 < N_NODES)
                *(__half2*)(C + (size_t)(r + 8) * F + c) =
                    __floats2half2_rn(acc[tm][tn][2], acc[tm][tn][3]);
        }
    }
}

// ------------------------------------------------------------------
// CSR pull aggregation: fp16 messages in, fp16 hidden out.
// fp32 accumulate, fused self-loop + bias + relu. warp per node.
// ------------------------------------------------------------------
__device__ __forceinline__ void acc_row(float4& acc, const __half* p, float nm) {
    uint2 u = *(const uint2*)p;
    __half2 h0 = *(__half2*)&u.x;
    __half2 h1 = *(__half2*)&u.y;
    float2 f0 = __half22float2(h0);
    float2 f1 = __half22float2(h1);
    acc.x += f0.x * nm; acc.y += f0.y * nm;
    acc.z += f1.x * nm; acc.w += f1.y * nm;
}

__global__ void __launch_bounds__(256) agg_csr_kernel(
    const __half* __restrict__ xw, __half* __restrict__ out,
    const float* __restrict__ bias) {
    int warp = (blockIdx.x * 256 + threadIdx.x) >> 5;
    int lane = threadIdx.x & 31;
    if (warp >= N_NODES) return;
    int node = warp;

    float di = g_dinv[node];
    float4 acc = make_float4(0.f, 0.f, 0.f, 0.f);

    // self loop
    acc_row(acc, xw + (size_t)node * F + lane * 4, di * di);

    int beg = g_rowptr[node];
    int end = g_rowptr[node + 1];

    int j = beg;
    for (; j + 3 < end; j += 4) {
        int2 p0 = g_epack[j];
        int2 p1 = g_epack[j + 1];
        int2 p2 = g_epack[j + 2];
        int2 p3 = g_epack[j + 3];
        acc_row(acc, xw + (size_t)p0.x * F + lane * 4, __int_as_float(p0.y));
        acc_row(acc, xw + (size_t)p1.x * F + lane * 4, __int_as_float(p1.y));
        acc_row(acc, xw + (size_t)p2.x * F + lane * 4, __int_as_float(p2.y));
        acc_row(acc, xw + (size_t)p3.x * F + lane * 4, __int_as_float(p3.y));
    }
    for (; j < end; j++) {
        int2 p0 = g_epack[j];
        acc_row(acc, xw + (size_t)p0.x * F + lane * 4, __int_as_float(p0.y));
    }

    float4 bb = ((const float4*)bias)[lane];
    acc.x = fmaxf(acc.x + bb.x, 0.f);
    acc.y = fmaxf(acc.y + bb.y, 0.f);
    acc.z = fmaxf(acc.z + bb.z, 0.f);
    acc.w = fmaxf(acc.w + bb.w, 0.f);
    __half2 h0 = __floats2half2_rn(acc.x, acc.y);
    __half2 h1 = __floats2half2_rn(acc.z, acc.w);
    *(uint2*)(out + (size_t)node * F + lane * 4) =
        make_uint2(h2bits(h0), h2bits(h1));
}

// ------------------------------------------------------------------
// fp16 classifier: out32[N,40] = A16[N,128] @ Wl[128,40] + bl
// 128-row block, 8 warps x 16 rows, 5 n-tiles, m16n8k16.
// ------------------------------------------------------------------
#define WH_STRIDE 44  // u32 stride: 40 n + pad

__global__ void __launch_bounds__(256) cls_f16_kernel(
    const __half* __restrict__ A, const float* __restrict__ Wl,
    const float* __restrict__ bl, float* __restrict__ out) {
    __shared__ uint32_t As[128 * AH_STRIDE];  // 10 KB
    __shared__ uint32_t Ws[64 * WH_STRIDE];   // 11 KB (k2 x n half2 pairs)

    int tid = threadIdx.x;
    int lane = tid & 31;
    int warp = tid >> 5;
    int g = lane >> 2;
    int tg = lane & 3;
    int row0 = blockIdx.x * 128;

    // load Wl (128x40) as half2 pairs along k: 64*40 = 2560 entries
    for (int j = tid; j < 64 * 40; j += 256) {
        int k2 = j / 40, n = j % 40;
        float w0 = Wl[(size_t)(k2 * 2) * NCLS + n];
        float w1 = Wl[(size_t)(k2 * 2 + 1) * NCLS + n];
        Ws[k2 * WH_STRIDE + n] = h2bits(__floats2half2_rn(w0, w1));
    }

    float acc[5][4];
#pragma unroll
    for (int tn = 0; tn < 5; tn++)
#pragma unroll
        for (int c = 0; c < 4; c++) acc[tn][c] = 0.0f;

#pragma unroll
    for (int kc = 0; kc < 4; kc++) {
#pragma unroll
        for (int i = 0; i < 2; i++) {
            int j = tid + i * 256;
            int r = j >> 2, q = j & 3;
            int grow = row0 + r;
            uint4 v = make_uint4(0, 0, 0, 0);
            if (grow < N_NODES)
                v = *(const uint4*)(A + (size_t)grow * F + kc * 32 + q * 8);
            *(uint2*)(As + r * AH_STRIDE + q * 4) = make_uint2(v.x, v.y);
            *(uint2*)(As + r * AH_STRIDE + q * 4 + 2) = make_uint2(v.z, v.w);
        }
        __syncthreads();

#pragma unroll
        for (int s = 0; s < 2; s++) {
            int rbase = warp * 16;
            const uint32_t* ap = As + s * 8 + tg;
            uint32_t a0 = ap[(rbase + g) * AH_STRIDE];
            uint32_t a1 = ap[(rbase + g + 8) * AH_STRIDE];
            uint32_t a2 = ap[(rbase + g) * AH_STRIDE + 4];
            uint32_t a3 = ap[(rbase + g + 8) * AH_STRIDE + 4];
            int k2base = kc * 16 + s * 8;
#pragma unroll
            for (int tn = 0; tn < 5; tn++) {
                int ncol = tn * 8 + g;
                uint32_t b0 = Ws[(k2base + tg) * WH_STRIDE + ncol];
                uint32_t b1 = Ws[(k2base + tg + 4) * WH_STRIDE + ncol];
                asm volatile(
                    "mma.sync.aligned.m16n8k16.row.col.f32.f16.f16.f32 "
                    "{%0,%1,%2,%3}, {%4,%5,%6,%7}, {%8,%9}, {%0,%1,%2,%3};"
                    : "+f"(acc[tn][0]), "+f"(acc[tn][1]),
                      "+f"(acc[tn][2]), "+f"(acc[tn][3])
                    : "r"(a0), "r"(a1), "r"(a2), "r"(a3), "r"(b0), "r"(b1));
            }
        }
        __syncthreads();
    }

#pragma unroll
    for (int tn = 0; tn < 5; tn++) {
        int r = row0 + warp * 16 + g;
        int c = tn * 8 + tg * 2;
        float2 bb = *(const float2*)(bl + c);
        if (r < N_NODES)
            *(float2*)(out + (size_t)r * NCLS + c) =
                make_float2(acc[tn][0] + bb.x, acc[tn][1] + bb.y);
        if (r + 8 < N_NODES)
            *(float2*)(out + (size_t)(r + 8) * NCLS + c) =
                make_float2(acc[tn][2] + bb.x, acc[tn][3] + bb.y);
    }
}

// ------------------------------------------------------------------
extern "C" void kernel_launch(void* const* d_in, const int* in_sizes, int n_in,
                              void* d_out, int out_size) {
    const float* X  = (const float*)d_in[0];
    const int*   EI = (const int*)d_in[1];   // [2, E]: src | dst
    const float* W1 = (const float*)d_in[2];
    const float* b1 = (const float*)d_in[3];
    const float* W2 = (const float*)d_in[4];
    const float* b2 = (const float*)d_in[5];
    const float* Wl = (const float*)d_in[6];
    const float* bl = (const float*)d_in[7];
    float* out = (float*)d_out;

    const int* src = EI;
    const int* dst = EI + N_EDGES;

    __half *hbuf, *hid;
    cudaGetSymbolAddress((void**)&hbuf, g_hbuf);
    cudaGetSymbolAddress((void**)&hid, g_hid);

    static cudaStream_t s2 = nullptr;
    static cudaEvent_t evF = nullptr, evJ = nullptr;
    if (s2 == nullptr) {
        cudaStreamCreateWithFlags(&s2, cudaStreamNonBlocking);
        cudaEventCreateWithFlags(&evF, cudaEventDisableTiming);
        cudaEventCreateWithFlags(&evJ, cudaEventDisableTiming);
    }

    const int T = 256;
    int nblk_nodes = (N_NODES + T - 1) / T;
    int nblk_edges = (N_EDGES + T - 1) / T;
    int nblk_gemm  = (N_NODES + 127) / 128;
    int nblk_agg   = (N_NODES * 32 + T - 1) / T;

    // ---- fork: CSR build + norm on s2, GEMM1 on main stream ----
    cudaEventRecord(evF, 0);
    cudaStreamWaitEvent(s2, evF, 0);

    zero_cnt_kernel<<<nblk_nodes, T, 0, s2>>>();
    hist_kernel<<<nblk_edges, T, 0, s2>>>(dst);
    dinv_partial_kernel<<<NBLK_SCAN, SCAN_CHUNK, 0, s2>>>();
    scan_top_kernel<<<1, 32, 0, s2>>>();
    scan_write_kernel<<<NBLK_SCAN, SCAN_CHUNK, 0, s2>>>();
    scatter_kernel<<<nblk_edges, T, 0, s2>>>(src, dst);
    cudaEventRecord(evJ, s2);

    gemm_tf32_kernel<<<nblk_gemm, T>>>(X, W1, hbuf);

    // ---- join ----
    cudaStreamWaitEvent(0, evJ, 0);

    // ---- layer 1 agg ----
    agg_csr_kernel<<<nblk_agg, T>>>(hbuf, hid, b1);

    // ---- layer 2 ----
    gemm_f16_kernel<<<nblk_gemm, T>>>(hid, W2, hbuf);
    agg_csr_kernel<<<nblk_agg, T>>>(hbuf, hid, b2);

    // ---- classifier ----
    cls_f16_kernel<<<nblk_gemm, T>>>(hid, Wl, bl, out);
}